// round 9
// baseline (speedup 1.0000x reference)
#include <cuda_runtime.h>

#define THREADS 512
#define TILE    128           // pixels per block
#define KC      128           // channels
#define NPIX    (16 * 8192)
#define CHUNK   32
#define DSMEM_FLOATS (3 * KC * TILE + CHUNK * KC)   // 53248 floats = 212992 B

typedef unsigned long long ull;

// Pre-transposed, BN-folded weights: g_Wt[s][k*128+o]; stages 0=cl1,1=reg1,2=cl2,3=cl3[0:128]
__device__ __align__(16) float g_Wt[4][KC * KC];
__device__ float g_bias[4][KC];

__device__ __forceinline__ float lrelu_f(float x) { return x >= 0.0f ? x : 0.01f * x; }

__device__ __forceinline__ ull packdup(float x) {
    ull r; asm("mov.b64 %0, {%1,%1};" : "=l"(r) : "f"(x)); return r;
}
__device__ __forceinline__ ull ffma2(ull a, ull b, ull c) {
    ull d; asm("fma.rn.f32x2 %0, %1, %2, %3;" : "=l"(d) : "l"(a), "l"(b), "l"(c)); return d;
}
__device__ __forceinline__ float2 unpack2(ull v) {
    float2 f; asm("mov.b64 {%0,%1}, %2;" : "=f"(f.x), "=f"(f.y) : "l"(v)); return f;
}

// ---------------- prep: transpose + BN-fold weights --------------------------------------
__global__ void prep_kernel(const float* __restrict__ cl1_w, const float* __restrict__ cl1_b,
                            const float* __restrict__ cl1_g, const float* __restrict__ cl1_bt,
                            const float* __restrict__ cl1_m, const float* __restrict__ cl1_v,
                            const float* __restrict__ cl2_w, const float* __restrict__ cl2_b,
                            const float* __restrict__ cl3_w, const float* __restrict__ cl3_b,
                            const float* __restrict__ reg1_w, const float* __restrict__ reg1_b,
                            const float* __restrict__ reg1_g, const float* __restrict__ reg1_bt,
                            const float* __restrict__ reg1_m, const float* __restrict__ reg1_v)
{
    int t = blockIdx.x * blockDim.x + threadIdx.x;
    if (t < 4 * KC * KC) {
        int s = t >> 14, idx = t & 16383, o = idx >> 7, k = idx & 127;
        const float* W = (s == 0) ? cl1_w : (s == 1) ? reg1_w : (s == 2) ? cl2_w : cl3_w;
        float sc = 1.0f;
        if (s == 0)      sc = cl1_g[o]  * rsqrtf(cl1_v[o]  + 1e-5f);
        else if (s == 1) sc = reg1_g[o] * rsqrtf(reg1_v[o] + 1e-5f);
        g_Wt[s][k * KC + o] = W[o * KC + k] * sc;
    }
    if (t < 4 * KC) {
        int s = t >> 7, o = t & 127;
        float b;
        if (s == 0)      b = (cl1_b[o]  - cl1_m[o])  * (cl1_g[o]  * rsqrtf(cl1_v[o]  + 1e-5f)) + cl1_bt[o];
        else if (s == 1) b = (reg1_b[o] - reg1_m[o]) * (reg1_g[o] * rsqrtf(reg1_v[o] + 1e-5f)) + reg1_bt[o];
        else if (s == 2) b = cl2_b[o];
        else             b = cl3_b[o];
        g_bias[s][o] = b;
    }
}

// ---------------- fused main kernel ------------------------------------------------------
__global__ __launch_bounds__(THREADS, 1)
void fused_head_kernel(const float* __restrict__ x_in,
                       const float* __restrict__ cl3_w, const float* __restrict__ cl3_b,
                       const float* __restrict__ w2,    const float* __restrict__ b2,
                       const float* __restrict__ w3,    const float* __restrict__ b3,
                       float* __restrict__ out)
{
    extern __shared__ float sm[];
    float* A  = sm;                      // 128ch x 128px : x, later x2
    float* Hs = sm + KC * TILE;          // h
    float* Rs = sm + 2 * KC * TILE;      // r
    float* Wb = sm + 3 * KC * TILE;      // 32k x 128o weight chunk (4096 floats)
    // aliases into Wb, used only after all GEMMs are done reading it:
    float* redv = Wb;                    // [16 warps][128 px]
    int*   redi = (int*)(Wb + 2048);     // [16][128]
    __shared__ float sbias[4][KC];
    __shared__ int   s_ind[TILE];
    __shared__ float s_pred[TILE][4];

    const int tid = threadIdx.x;
    const int og  = tid >> 4;            // 0..31 : o-block of 4
    const int pg  = tid & 15;            // 0..15
    // this thread's pixel pairs: px = pg*2 + e + jj*32  (jj=0..3, e=0,1)
    const int gp0 = blockIdx.x * TILE;
    const int bb  = gp0 >> 13;
    const int w0  = gp0 & 8191;

    if (tid < KC) {
#pragma unroll
        for (int s = 0; s < 4; s++) sbias[s][tid] = g_bias[s][tid];
    }
    // x tile: A[c*128 + j] = x_in[bb, c, 0, w0 + j]   (float4 coalesced)
    {
        const float4* xsrc = (const float4*)(x_in + ((size_t)bb * KC) * 8192 + w0);
        float4* ad = (float4*)A;
        for (int i = tid; i < KC * TILE / 4; i += THREADS) {
            int c = i >> 5, j4 = i & 31;
            ad[c * 32 + j4] = xsrc[c * 2048 + j4];
        }
    }

    ull acc[4][4];   // 4 o x 4 px-pairs (pair jj at px = pg*2 + jj*32)

#pragma unroll 1
    for (int s = 0; s < 4; s++) {
        const float* Wt  = g_Wt[s];
        const float* src = (s == 2) ? Hs : A;     // 0:x 1:x 2:h 3:x2(in A)
#pragma unroll
        for (int i = 0; i < 4; i++)
#pragma unroll
            for (int jj = 0; jj < 4; jj++) acc[i][jj] = 0ULL;

#pragma unroll 1
        for (int c0 = 0; c0 < KC; c0 += CHUNK) {
            __syncthreads();
            {   // stage 32x128 weight chunk (4096 floats = 1024 float4)
                const float4* ws = (const float4*)(Wt + (c0 << 7));
                float4* wd = (float4*)Wb;
                wd[tid]       = ws[tid];
                wd[tid + 512] = ws[tid + 512];
            }
            __syncthreads();
#pragma unroll 4
            for (int kk = 0; kk < CHUNK; kk++) {
                float4 a0 = *(const float4*)(Wb + (kk << 7) + (og << 2));  // 2-addr bcast
                const ull* bq = (const ull*)(src + ((c0 + kk) << 7));
                ull bA = bq[pg];          // 16 lanes x 8B contiguous, upper half dup
                ull bB = bq[pg + 16];
                ull bC = bq[pg + 32];
                ull bD = bq[pg + 48];
                float aval[4] = {a0.x, a0.y, a0.z, a0.w};
#pragma unroll
                for (int i = 0; i < 4; i++) {
                    ull av = packdup(aval[i]);
                    acc[i][0] = ffma2(av, bA, acc[i][0]);
                    acc[i][1] = ffma2(av, bB, acc[i][1]);
                    acc[i][2] = ffma2(av, bC, acc[i][2]);
                    acc[i][3] = ffma2(av, bD, acc[i][3]);
                }
            }
        }
        if (s < 3) {
            float* dst = (s == 0) ? Hs : (s == 1) ? Rs : A;
#pragma unroll
            for (int i = 0; i < 4; i++) {
                int o = og * 4 + i;
                float bo = sbias[s][o];
                float* dp = dst + o * TILE + pg * 2;
#pragma unroll
                for (int jj = 0; jj < 4; jj++) {
                    float2 v = unpack2(acc[i][jj]);
                    v.x = lrelu_f(v.x + bo);
                    v.y = lrelu_f(v.y + bo);
                    *(float2*)(dp + jj * 32) = v;     // conflict-free STS.64
                }
            }
        }
    }

    // -------- argmax over 128 logits (acc = cl3: o in og*4.., px = pg*2+e+jj*32) --------
    __syncthreads();    // all warps done with Wb weights -> safe to alias
    float bv[8]; int bi[8];
#pragma unroll
    for (int j = 0; j < 8; j++) { bv[j] = -3.4e38f; bi[j] = 0; }
#pragma unroll
    for (int i = 0; i < 4; i++) {
        int o = og * 4 + i;
        float bo = sbias[3][o];
#pragma unroll
        for (int jj = 0; jj < 4; jj++) {
            float2 v = unpack2(acc[i][jj]);
            float v0 = v.x + bo, v1 = v.y + bo;
            if (v0 > bv[2 * jj])     { bv[2 * jj] = v0;     bi[2 * jj] = o; }
            if (v1 > bv[2 * jj + 1]) { bv[2 * jj + 1] = v1; bi[2 * jj + 1] = o; }
        }
    }
    // lanes l and l^16 share pg (og differs by 1) -> merge, tie keeps smaller o
#pragma unroll
    for (int j = 0; j < 8; j++) {
        float ov = __shfl_xor_sync(0xFFFFFFFFu, bv[j], 16);
        int   oi = __shfl_xor_sync(0xFFFFFFFFu, bi[j], 16);
        if (ov > bv[j] || (ov == bv[j] && oi < bi[j])) { bv[j] = ov; bi[j] = oi; }
    }
    {
        int lane = tid & 31, w = tid >> 5;      // warp w holds o-block [w*8, w*8+8)
        if (lane < 16) {
#pragma unroll
            for (int j = 0; j < 8; j++) {
                int px = lane * 2 + (j & 1) + (j >> 1) * 32;
                redv[w * TILE + px] = bv[j];
                redi[w * TILE + px] = bi[j];
            }
        }
    }
    __syncthreads();
    if (tid < TILE) {
        int p = tid;
        float mv = redv[p]; int mi = redi[p];
#pragma unroll
        for (int w = 1; w < 16; w++) {          // w ascending == o ascending
            float v = redv[w * TILE + p]; int ii = redi[w * TILE + p];
            if (v > mv || (v == mv && ii < mi)) { mv = v; mi = ii; }
        }
        s_ind[p] = mi;
        // mask channel: row 128 of cl3_w against x2 (in A)
        const float* mrow = cl3_w + 128 * KC;
        float macc = __ldg(cl3_b + 128);
#pragma unroll 4
        for (int k = 0; k < KC; k++)
            macc = fmaf(__ldg(mrow + k), A[k * TILE + p], macc);
        out[NPIX + gp0 + p] = lrelu_f(macc);
    }
    __syncthreads();

    // -------- stage 5: y = lrelu(cat[r;h] @ w2[sp] + b2[sp]); reg = y . w3[ind] ---------
    {
        int q  = tid >> 7;                // 0..3 -> outputs q*8 .. q*8+8
        int p  = tid & 127;
        int ind = s_ind[p];
        int sp  = ind >> 4;
        const float* wp = w2 + (size_t)sp * (256 * 32) + q * 8;
        const ulonglong2* binit = (const ulonglong2*)(b2 + sp * 32 + q * 8);
        ulonglong2 t0 = binit[0], t1 = binit[1];
        ull y[4] = { t0.x, t0.y, t1.x, t1.y };
#pragma unroll 4
        for (int f = 0; f < 128; f++) {
            ull c = packdup(Rs[f * TILE + p]);
            const ulonglong2* wq = (const ulonglong2*)(wp + f * 32);
            ulonglong2 u0 = wq[0], u1 = wq[1];
            y[0] = ffma2(c, u0.x, y[0]); y[1] = ffma2(c, u0.y, y[1]);
            y[2] = ffma2(c, u1.x, y[2]); y[3] = ffma2(c, u1.y, y[3]);
        }
#pragma unroll 4
        for (int f = 0; f < 128; f++) {
            ull c = packdup(Hs[f * TILE + p]);
            const ulonglong2* wq = (const ulonglong2*)(wp + (128 + f) * 32);
            ulonglong2 u0 = wq[0], u1 = wq[1];
            y[0] = ffma2(c, u0.x, y[0]); y[1] = ffma2(c, u0.y, y[1]);
            y[2] = ffma2(c, u1.x, y[2]); y[3] = ffma2(c, u1.y, y[3]);
        }
        const float* w3p = w3 + ind * 32 + q * 8;
        float part = 0.0f;
#pragma unroll
        for (int r = 0; r < 4; r++) {
            float2 v = unpack2(y[r]);
            part = fmaf(lrelu_f(v.x), __ldg(w3p + 2 * r),     part);
            part = fmaf(lrelu_f(v.y), __ldg(w3p + 2 * r + 1), part);
        }
        s_pred[p][q] = part;
    }
    __syncthreads();
    if (tid < TILE) {
        int p = tid;
        int ind = s_ind[p];
        float reg = s_pred[p][0] + s_pred[p][1] + s_pred[p][2] + s_pred[p][3] + __ldg(b3 + ind);
        out[gp0 + p] = ((float)ind + reg) * 0.0078125f;
    }
}

extern "C" void kernel_launch(void* const* d_in, const int* in_sizes, int n_in,
                              void* d_out, int out_size) {
    if (n_in < 21 || d_out == nullptr) return;

    const float* x_in    = (const float*)d_in[0];
    const float* cl1_w   = (const float*)d_in[1];
    const float* cl1_b   = (const float*)d_in[2];
    const float* cl1_g   = (const float*)d_in[3];
    const float* cl1_bt  = (const float*)d_in[4];
    const float* cl1_m   = (const float*)d_in[5];
    const float* cl1_v   = (const float*)d_in[6];
    const float* cl2_w   = (const float*)d_in[7];
    const float* cl2_b   = (const float*)d_in[8];
    const float* cl3_w   = (const float*)d_in[9];
    const float* cl3_b   = (const float*)d_in[10];
    const float* reg1_w  = (const float*)d_in[11];
    const float* reg1_b  = (const float*)d_in[12];
    const float* reg1_g  = (const float*)d_in[13];
    const float* reg1_bt = (const float*)d_in[14];
    const float* reg1_m  = (const float*)d_in[15];
    const float* reg1_v  = (const float*)d_in[16];
    const float* w2      = (const float*)d_in[17];
    const float* b2      = (const float*)d_in[18];
    const float* w3      = (const float*)d_in[19];
    const float* b3      = (const float*)d_in[20];
    float* out = (float*)d_out;

    prep_kernel<<<(4 * 128 * 128 + 255) / 256, 256>>>(
        cl1_w, cl1_b, cl1_g, cl1_bt, cl1_m, cl1_v,
        cl2_w, cl2_b, cl3_w, cl3_b,
        reg1_w, reg1_b, reg1_g, reg1_bt, reg1_m, reg1_v);

    size_t smem = (size_t)DSMEM_FLOATS * sizeof(float);   // 212,992 B
    cudaFuncSetAttribute(fused_head_kernel,
                         cudaFuncAttributeMaxDynamicSharedMemorySize, (int)smem);
    fused_head_kernel<<<NPIX / TILE, THREADS, smem>>>(
        x_in, cl3_w, cl3_b, w2, b2, w3, b3, out);
}

// round 10
// speedup vs baseline: 1.0171x; 1.0171x over previous
#include <cuda_runtime.h>

#define THREADS 512
#define TILE    128           // pixels per block
#define KC      128           // channels
#define NPIX    (16 * 8192)
#define DSMEM_FLOATS (3 * KC * TILE + 4096)   // 53248 floats = 212992 B

typedef unsigned long long ull;

// Pre-transposed, BN-folded weights: g_Wt[s][k*128+o]; stages 0=cl1,1=reg1,2=cl2,3=cl3[0:128]
__device__ __align__(16) float g_Wt[4][KC * KC];
__device__ float g_bias[4][KC];

__device__ __forceinline__ float lrelu_f(float x) { return x >= 0.0f ? x : 0.01f * x; }

__device__ __forceinline__ ull packdup(float x) {
    ull r; asm("mov.b64 %0, {%1,%1};" : "=l"(r) : "f"(x)); return r;
}
__device__ __forceinline__ ull ffma2(ull a, ull b, ull c) {
    ull d; asm("fma.rn.f32x2 %0, %1, %2, %3;" : "=l"(d) : "l"(a), "l"(b), "l"(c)); return d;
}
__device__ __forceinline__ float2 unpack2(ull v) {
    float2 f; asm("mov.b64 {%0,%1}, %2;" : "=f"(f.x), "=f"(f.y) : "l"(v)); return f;
}

// ---------------- prep: transpose + BN-fold weights --------------------------------------
__global__ void prep_kernel(const float* __restrict__ cl1_w, const float* __restrict__ cl1_b,
                            const float* __restrict__ cl1_g, const float* __restrict__ cl1_bt,
                            const float* __restrict__ cl1_m, const float* __restrict__ cl1_v,
                            const float* __restrict__ cl2_w, const float* __restrict__ cl2_b,
                            const float* __restrict__ cl3_w, const float* __restrict__ cl3_b,
                            const float* __restrict__ reg1_w, const float* __restrict__ reg1_b,
                            const float* __restrict__ reg1_g, const float* __restrict__ reg1_bt,
                            const float* __restrict__ reg1_m, const float* __restrict__ reg1_v)
{
    int t = blockIdx.x * blockDim.x + threadIdx.x;
    if (t < 4 * KC * KC) {
        int s = t >> 14, idx = t & 16383, o = idx >> 7, k = idx & 127;
        const float* W = (s == 0) ? cl1_w : (s == 1) ? reg1_w : (s == 2) ? cl2_w : cl3_w;
        float sc = 1.0f;
        if (s == 0)      sc = cl1_g[o]  * rsqrtf(cl1_v[o]  + 1e-5f);
        else if (s == 1) sc = reg1_g[o] * rsqrtf(reg1_v[o] + 1e-5f);
        g_Wt[s][k * KC + o] = W[o * KC + k] * sc;
    }
    if (t < 4 * KC) {
        int s = t >> 7, o = t & 127;
        float b;
        if (s == 0)      b = (cl1_b[o]  - cl1_m[o])  * (cl1_g[o]  * rsqrtf(cl1_v[o]  + 1e-5f)) + cl1_bt[o];
        else if (s == 1) b = (reg1_b[o] - reg1_m[o]) * (reg1_g[o] * rsqrtf(reg1_v[o] + 1e-5f)) + reg1_bt[o];
        else if (s == 2) b = cl2_b[o];
        else             b = cl3_b[o];
        g_bias[s][o] = b;
    }
}

// ---------------- fused main kernel ------------------------------------------------------
__global__ __launch_bounds__(THREADS, 1)
void fused_head_kernel(const float* __restrict__ x_in,
                       const float* __restrict__ cl3_w, const float* __restrict__ cl3_b,
                       const float* __restrict__ w2,    const float* __restrict__ b2,
                       const float* __restrict__ w3,    const float* __restrict__ b3,
                       float* __restrict__ out)
{
    extern __shared__ float sm[];
    float* A  = sm;                      // 128ch x 128px : x, later x2
    float* Hs = sm + KC * TILE;          // h
    float* Rs = sm + 2 * KC * TILE;      // r
    float* Wb = sm + 3 * KC * TILE;      // weight chunk buffer (4096 floats)
    // aliases into Wb, used only after all GEMMs are done reading it:
    float* redv = Wb;                    // [16 warps][128 px]
    int*   redi = (int*)(Wb + 2048);     // [16][128]
    __shared__ float sbias[4][KC];
    __shared__ int   s_ind[TILE];
    __shared__ float s_pred[TILE][4];

    const int tid = threadIdx.x;
    const int og  = tid >> 4;            // 0..31 : o-quad index
    const int pg  = tid & 15;            // 0..15
    // this thread's pixels: px = pg*4 + e + jj*64   (jj=0,1; e=0..3)
    const int gp0 = blockIdx.x * TILE;
    const int bb  = gp0 >> 13;
    const int w0  = gp0 & 8191;

    if (tid < KC) {
#pragma unroll
        for (int s = 0; s < 4; s++) sbias[s][tid] = g_bias[s][tid];
    }
    // x tile: A[c*128 + j] = x_in[bb, c, 0, w0 + j]   (float4 coalesced)
    {
        const float4* xsrc = (const float4*)(x_in + ((size_t)bb * KC) * 8192 + w0);
        float4* ad = (float4*)A;
        for (int i = tid; i < KC * TILE / 4; i += THREADS) {
            int c = i >> 5, j4 = i & 31;
            ad[c * 32 + j4] = xsrc[c * 2048 + j4];
        }
    }

    // =================== fused stage 0+1: cl1 & reg1 (both read x in A) ==================
    {
        ull acc[2][4][4];    // [stage][o][pair]  pair pp: px = pg*4 + (pp>>1)*64 + (pp&1)*2
#pragma unroll
        for (int st = 0; st < 2; st++)
#pragma unroll
            for (int i = 0; i < 4; i++)
#pragma unroll
                for (int pp = 0; pp < 4; pp++) acc[st][i][pp] = 0ULL;

#pragma unroll 1
        for (int c0 = 0; c0 < KC; c0 += 16) {
            __syncthreads();
            // stage 16k x (128 cl1 + 128 reg1) interleaved: Wb[k][0:128]=cl1, [128:256]=reg1
            for (int i = tid; i < 1024; i += THREADS) {
                int k = i >> 6, f = i & 63;
                const float4* sp4 = (f < 32)
                    ? ((const float4*)(g_Wt[0] + (size_t)(c0 + k) * KC) + f)
                    : ((const float4*)(g_Wt[1] + (size_t)(c0 + k) * KC) + (f - 32));
                ((float4*)Wb)[i] = *sp4;
            }
            __syncthreads();
#pragma unroll 4
            for (int kk = 0; kk < 16; kk++) {
                const float* wrow = Wb + (kk << 8);
                float4 a0 = *(const float4*)(wrow + (og << 2));          // cl1 quad
                float4 a1 = *(const float4*)(wrow + 128 + (og << 2));    // reg1 quad
                const float* brow = A + ((c0 + kk) << 7);
                ulonglong2 b0 = *(const ulonglong2*)(brow + (pg << 2));        // px pg*4+0..3
                ulonglong2 b1 = *(const ulonglong2*)(brow + 64 + (pg << 2));   // px +64
                float av0[4] = {a0.x, a0.y, a0.z, a0.w};
                float av1[4] = {a1.x, a1.y, a1.z, a1.w};
#pragma unroll
                for (int i = 0; i < 4; i++) {
                    ull d0 = packdup(av0[i]);
                    acc[0][i][0] = ffma2(d0, b0.x, acc[0][i][0]);
                    acc[0][i][1] = ffma2(d0, b0.y, acc[0][i][1]);
                    acc[0][i][2] = ffma2(d0, b1.x, acc[0][i][2]);
                    acc[0][i][3] = ffma2(d0, b1.y, acc[0][i][3]);
                    ull d1 = packdup(av1[i]);
                    acc[1][i][0] = ffma2(d1, b0.x, acc[1][i][0]);
                    acc[1][i][1] = ffma2(d1, b0.y, acc[1][i][1]);
                    acc[1][i][2] = ffma2(d1, b1.x, acc[1][i][2]);
                    acc[1][i][3] = ffma2(d1, b1.y, acc[1][i][3]);
                }
            }
        }
        // epilogue: Hs = lrelu(cl1), Rs = lrelu(reg1)
#pragma unroll
        for (int st = 0; st < 2; st++) {
            float* dst = (st == 0) ? Hs : Rs;
#pragma unroll
            for (int i = 0; i < 4; i++) {
                int o = og * 4 + i;
                float bo = sbias[st][o];
                float* dp = dst + o * TILE + pg * 4;
#pragma unroll
                for (int jj = 0; jj < 2; jj++) {
                    float2 u = unpack2(acc[st][i][jj * 2]);
                    float2 v = unpack2(acc[st][i][jj * 2 + 1]);
                    float4 w4;
                    w4.x = lrelu_f(u.x + bo); w4.y = lrelu_f(u.y + bo);
                    w4.z = lrelu_f(v.x + bo); w4.w = lrelu_f(v.y + bo);
                    *(float4*)(dp + jj * 64) = w4;
                }
            }
        }
    }

    ull acc[4][4];   // reused by stage 2 and stage 3

    // =================== stage 2: x2 = lrelu(cl2 @ h) -> A ==============================
    {
#pragma unroll
        for (int i = 0; i < 4; i++)
#pragma unroll
            for (int pp = 0; pp < 4; pp++) acc[i][pp] = 0ULL;
#pragma unroll 1
        for (int c0 = 0; c0 < KC; c0 += 32) {
            __syncthreads();
            {   // stage 32k x 128o chunk of cl2
                const float4* ws = (const float4*)(g_Wt[2] + ((size_t)c0 << 7));
                float4* wd = (float4*)Wb;
                wd[tid]       = ws[tid];
                wd[tid + 512] = ws[tid + 512];
            }
            __syncthreads();
#pragma unroll 4
            for (int kk = 0; kk < 32; kk++) {
                float4 a0 = *(const float4*)(Wb + (kk << 7) + (og << 2));
                const float* brow = Hs + ((c0 + kk) << 7);
                ulonglong2 b0 = *(const ulonglong2*)(brow + (pg << 2));
                ulonglong2 b1 = *(const ulonglong2*)(brow + 64 + (pg << 2));
                float av[4] = {a0.x, a0.y, a0.z, a0.w};
#pragma unroll
                for (int i = 0; i < 4; i++) {
                    ull d = packdup(av[i]);
                    acc[i][0] = ffma2(d, b0.x, acc[i][0]);
                    acc[i][1] = ffma2(d, b0.y, acc[i][1]);
                    acc[i][2] = ffma2(d, b1.x, acc[i][2]);
                    acc[i][3] = ffma2(d, b1.y, acc[i][3]);
                }
            }
        }
        __syncthreads();   // all reads of A (x) done in stage 0+1; safe to overwrite
#pragma unroll
        for (int i = 0; i < 4; i++) {
            int o = og * 4 + i;
            float bo = sbias[2][o];
            float* dp = A + o * TILE + pg * 4;
#pragma unroll
            for (int jj = 0; jj < 2; jj++) {
                float2 u = unpack2(acc[i][jj * 2]);
                float2 v = unpack2(acc[i][jj * 2 + 1]);
                float4 w4;
                w4.x = lrelu_f(u.x + bo); w4.y = lrelu_f(u.y + bo);
                w4.z = lrelu_f(v.x + bo); w4.w = lrelu_f(v.y + bo);
                *(float4*)(dp + jj * 64) = w4;
            }
        }
    }

    // =================== stage 3: logits = cl3[0:128] @ x2 (in A) =======================
    {
#pragma unroll
        for (int i = 0; i < 4; i++)
#pragma unroll
            for (int pp = 0; pp < 4; pp++) acc[i][pp] = 0ULL;
#pragma unroll 1
        for (int c0 = 0; c0 < KC; c0 += 32) {
            __syncthreads();
            {
                const float4* ws = (const float4*)(g_Wt[3] + ((size_t)c0 << 7));
                float4* wd = (float4*)Wb;
                wd[tid]       = ws[tid];
                wd[tid + 512] = ws[tid + 512];
            }
            __syncthreads();
#pragma unroll 4
            for (int kk = 0; kk < 32; kk++) {
                float4 a0 = *(const float4*)(Wb + (kk << 7) + (og << 2));
                const float* brow = A + ((c0 + kk) << 7);
                ulonglong2 b0 = *(const ulonglong2*)(brow + (pg << 2));
                ulonglong2 b1 = *(const ulonglong2*)(brow + 64 + (pg << 2));
                float av[4] = {a0.x, a0.y, a0.z, a0.w};
#pragma unroll
                for (int i = 0; i < 4; i++) {
                    ull d = packdup(av[i]);
                    acc[i][0] = ffma2(d, b0.x, acc[i][0]);
                    acc[i][1] = ffma2(d, b0.y, acc[i][1]);
                    acc[i][2] = ffma2(d, b1.x, acc[i][2]);
                    acc[i][3] = ffma2(d, b1.y, acc[i][3]);
                }
            }
        }
    }

    // -------- argmax over 128 logits; px of value j: pg*4 + (j&3) + (j>>2)*64 -----------
    __syncthreads();    // all warps done with Wb weights -> safe to alias
    float bv[8]; int bi[8];
#pragma unroll
    for (int j = 0; j < 8; j++) { bv[j] = -3.4e38f; bi[j] = 0; }
#pragma unroll
    for (int i = 0; i < 4; i++) {
        int o = og * 4 + i;
        float bo = sbias[3][o];
#pragma unroll
        for (int pp = 0; pp < 4; pp++) {
            float2 v = unpack2(acc[i][pp]);
            int j0 = (pp >> 1) * 4 + (pp & 1) * 2;    // e = (pp&1)*2 + {0,1}
            float v0 = v.x + bo, v1 = v.y + bo;
            if (v0 > bv[j0])     { bv[j0] = v0;     bi[j0] = o; }
            if (v1 > bv[j0 + 1]) { bv[j0 + 1] = v1; bi[j0 + 1] = o; }
        }
    }
    // lanes l and l^16 share pg (og differs by 1) -> merge, tie keeps smaller o
#pragma unroll
    for (int j = 0; j < 8; j++) {
        float ov = __shfl_xor_sync(0xFFFFFFFFu, bv[j], 16);
        int   oi = __shfl_xor_sync(0xFFFFFFFFu, bi[j], 16);
        if (ov > bv[j] || (ov == bv[j] && oi < bi[j])) { bv[j] = ov; bi[j] = oi; }
    }
    {
        int lane = tid & 31, w = tid >> 5;      // warp w holds o-block [w*8, w*8+8)
        if (lane < 16) {
#pragma unroll
            for (int j = 0; j < 8; j++) {
                int px = lane * 4 + (j & 3) + (j >> 2) * 64;
                redv[w * TILE + px] = bv[j];
                redi[w * TILE + px] = bi[j];
            }
        }
    }
    __syncthreads();
    if (tid < TILE) {
        int p = tid;
        float mv = redv[p]; int mi = redi[p];
#pragma unroll
        for (int w = 1; w < 16; w++) {          // w ascending == o ascending
            float v = redv[w * TILE + p]; int ii = redi[w * TILE + p];
            if (v > mv || (v == mv && ii < mi)) { mv = v; mi = ii; }
        }
        s_ind[p] = mi;
        // mask channel: row 128 of cl3_w against x2 (in A)
        const float* mrow = cl3_w + 128 * KC;
        float macc = __ldg(cl3_b + 128);
#pragma unroll 4
        for (int k = 0; k < KC; k++)
            macc = fmaf(__ldg(mrow + k), A[k * TILE + p], macc);
        out[NPIX + gp0 + p] = lrelu_f(macc);
    }
    __syncthreads();

    // -------- stage 5: y = lrelu(cat[r;h] @ w2[sp] + b2[sp]); reg = y . w3[ind] ---------
    {
        int q  = tid >> 7;                // 0..3 -> outputs q*8 .. q*8+8
        int p  = tid & 127;
        int ind = s_ind[p];
        int sp  = ind >> 4;
        const float* wp = w2 + (size_t)sp * (256 * 32) + q * 8;
        const ulonglong2* binit = (const ulonglong2*)(b2 + sp * 32 + q * 8);
        ulonglong2 t0 = binit[0], t1 = binit[1];
        ull y[4] = { t0.x, t0.y, t1.x, t1.y };
#pragma unroll 4
        for (int f = 0; f < 128; f++) {
            ull c = packdup(Rs[f * TILE + p]);
            const ulonglong2* wq = (const ulonglong2*)(wp + f * 32);
            ulonglong2 u0 = wq[0], u1 = wq[1];
            y[0] = ffma2(c, u0.x, y[0]); y[1] = ffma2(c, u0.y, y[1]);
            y[2] = ffma2(c, u1.x, y[2]); y[3] = ffma2(c, u1.y, y[3]);
        }
#pragma unroll 4
        for (int f = 0; f < 128; f++) {
            ull c = packdup(Hs[f * TILE + p]);
            const ulonglong2* wq = (const ulonglong2*)(wp + (128 + f) * 32);
            ulonglong2 u0 = wq[0], u1 = wq[1];
            y[0] = ffma2(c, u0.x, y[0]); y[1] = ffma2(c, u0.y, y[1]);
            y[2] = ffma2(c, u1.x, y[2]); y[3] = ffma2(c, u1.y, y[3]);
        }
        const float* w3p = w3 + ind * 32 + q * 8;
        float part = 0.0f;
#pragma unroll
        for (int r = 0; r < 4; r++) {
            float2 v = unpack2(y[r]);
            part = fmaf(lrelu_f(v.x), __ldg(w3p + 2 * r),     part);
            part = fmaf(lrelu_f(v.y), __ldg(w3p + 2 * r + 1), part);
        }
        s_pred[p][q] = part;
    }
    __syncthreads();
    if (tid < TILE) {
        int p = tid;
        int ind = s_ind[p];
        float reg = s_pred[p][0] + s_pred[p][1] + s_pred[p][2] + s_pred[p][3] + __ldg(b3 + ind);
        out[gp0 + p] = ((float)ind + reg) * 0.0078125f;
    }
}

extern "C" void kernel_launch(void* const* d_in, const int* in_sizes, int n_in,
                              void* d_out, int out_size) {
    if (n_in < 21 || d_out == nullptr) return;

    const float* x_in    = (const float*)d_in[0];
    const float* cl1_w   = (const float*)d_in[1];
    const float* cl1_b   = (const float*)d_in[2];
    const float* cl1_g   = (const float*)d_in[3];
    const float* cl1_bt  = (const float*)d_in[4];
    const float* cl1_m   = (const float*)d_in[5];
    const float* cl1_v   = (const float*)d_in[6];
    const float* cl2_w   = (const float*)d_in[7];
    const float* cl2_b   = (const float*)d_in[8];
    const float* cl3_w   = (const float*)d_in[9];
    const float* cl3_b   = (const float*)d_in[10];
    const float* reg1_w  = (const float*)d_in[11];
    const float* reg1_b  = (const float*)d_in[12];
    const float* reg1_g  = (const float*)d_in[13];
    const float* reg1_bt = (const float*)d_in[14];
    const float* reg1_m  = (const float*)d_in[15];
    const float* reg1_v  = (const float*)d_in[16];
    const float* w2      = (const float*)d_in[17];
    const float* b2      = (const float*)d_in[18];
    const float* w3      = (const float*)d_in[19];
    const float* b3      = (const float*)d_in[20];
    float* out = (float*)d_out;

    prep_kernel<<<(4 * 128 * 128 + 255) / 256, 256>>>(
        cl1_w, cl1_b, cl1_g, cl1_bt, cl1_m, cl1_v,
        cl2_w, cl2_b, cl3_w, cl3_b,
        reg1_w, reg1_b, reg1_g, reg1_bt, reg1_m, reg1_v);

    size_t smem = (size_t)DSMEM_FLOATS * sizeof(float);   // 212,992 B
    cudaFuncSetAttribute(fused_head_kernel,
                         cudaFuncAttributeMaxDynamicSharedMemorySize, (int)smem);
    fused_head_kernel<<<NPIX / TILE, THREADS, smem>>>(
        x_in, cl3_w, cl3_b, w2, b2, w3, b3, out);
}